// round 2
// baseline (speedup 1.0000x reference)
#include <cuda_runtime.h>
#include <cuda_bf16.h>

// Accumulators: [0] = sum(sq*mask), [1] = mask count, [2] = sum(sq)
__device__ double g_acc[3];

__global__ void zero_acc_kernel() {
    g_acc[0] = 0.0;
    g_acc[1] = 0.0;
    g_acc[2] = 0.0;
}

// Processes N elements, 4 per thread per grid-stride iteration.
// inputs is (N, 2) float32 -> read as float4 pairs (2 elements per float4).
// lik[i] = inputs[2*i + 1]  (channel index 1, since C == 2).
// mask is int32 per element (harness ships bool as int32).
__global__ __launch_bounds__(256) void topo_loss_reduce_kernel(
    const float4* __restrict__ inp,   // N/2 float4s (each holds 2 elements x 2 channels)
    const float4* __restrict__ w,     // N/4 float4s
    const float4* __restrict__ ref,   // N/4 float4s
    const int4*   __restrict__ mask,  // N/4 int4s
    int n4)                           // N / 4
{
    float sm = 0.0f;   // masked sum of sq_err
    float sf = 0.0f;   // full sum of sq_err
    int   cnt = 0;     // mask count

    const int stride = gridDim.x * blockDim.x;
    for (int i = blockIdx.x * blockDim.x + threadIdx.x; i < n4; i += stride) {
        // 4 logical elements: elements 4i..4i+3
        float4 a = inp[2 * i];       // elems 4i, 4i+1 : (c0, c1, c0, c1)
        float4 b = inp[2 * i + 1];   // elems 4i+2, 4i+3
        float4 wv = w[i];
        float4 rv = ref[i];
        int4   mv = mask[i];

        float e0 = a.y * wv.x - rv.x;
        float e1 = a.w * wv.y - rv.y;
        float e2 = b.y * wv.z - rv.z;
        float e3 = b.w * wv.w - rv.w;

        float s0 = e0 * e0;
        float s1 = e1 * e1;
        float s2 = e2 * e2;
        float s3 = e3 * e3;

        sf += s0 + s1 + s2 + s3;

        float m0 = mv.x ? 1.0f : 0.0f;
        float m1 = mv.y ? 1.0f : 0.0f;
        float m2 = mv.z ? 1.0f : 0.0f;
        float m3 = mv.w ? 1.0f : 0.0f;

        sm += s0 * m0 + s1 * m1 + s2 * m2 + s3 * m3;
        cnt += (mv.x ? 1 : 0) + (mv.y ? 1 : 0) + (mv.z ? 1 : 0) + (mv.w ? 1 : 0);
    }

    // Warp reduction
    #pragma unroll
    for (int off = 16; off > 0; off >>= 1) {
        sm  += __shfl_down_sync(0xFFFFFFFFu, sm, off);
        sf  += __shfl_down_sync(0xFFFFFFFFu, sf, off);
        cnt += __shfl_down_sync(0xFFFFFFFFu, cnt, off);
    }

    // Block reduction across warps
    __shared__ float s_sm[8];
    __shared__ float s_sf[8];
    __shared__ int   s_cnt[8];

    const int lane = threadIdx.x & 31;
    const int wid  = threadIdx.x >> 5;
    if (lane == 0) {
        s_sm[wid]  = sm;
        s_sf[wid]  = sf;
        s_cnt[wid] = cnt;
    }
    __syncthreads();

    if (wid == 0) {
        const int nwarps = blockDim.x >> 5;
        float bsm  = (lane < nwarps) ? s_sm[lane]  : 0.0f;
        float bsf  = (lane < nwarps) ? s_sf[lane]  : 0.0f;
        int   bcnt = (lane < nwarps) ? s_cnt[lane] : 0;
        #pragma unroll
        for (int off = 4; off > 0; off >>= 1) {
            bsm  += __shfl_down_sync(0xFFFFFFFFu, bsm, off);
            bsf  += __shfl_down_sync(0xFFFFFFFFu, bsf, off);
            bcnt += __shfl_down_sync(0xFFFFFFFFu, bcnt, off);
        }
        if (lane == 0) {
            atomicAdd(&g_acc[0], (double)bsm);
            atomicAdd(&g_acc[1], (double)bcnt);
            atomicAdd(&g_acc[2], (double)bsf);
        }
    }
}

__global__ void finalize_kernel(float* __restrict__ out, int n_total) {
    double n_masked = g_acc[1];
    double masked_mean = g_acc[0] / (n_masked > 1.0 ? n_masked : 1.0);
    double full_mean   = g_acc[2] / (double)n_total;
    out[0] = (float)((n_masked > 0.0) ? masked_mean : full_mean);
}

extern "C" void kernel_launch(void* const* d_in, const int* in_sizes, int n_in,
                              void* d_out, int out_size) {
    // Input order (per setup_inputs):
    //   0: inputs             (N*2 float32)
    //   1: topo_cp_weight_map (N float32)
    //   2: topo_cp_ref_map    (N float32)
    //   3: topo_mask          (N int32, 0/1)
    //   4: height, 5: width, 6: batch_size (unused; N comes from in_sizes[1])
    const float4* inp  = (const float4*)d_in[0];
    const float4* w    = (const float4*)d_in[1];
    const float4* ref  = (const float4*)d_in[2];
    const int4*   mask = (const int4*)d_in[3];
    float* out = (float*)d_out;

    const int n  = in_sizes[1];   // total elements (B*H*W)
    const int n4 = n / 4;

    zero_acc_kernel<<<1, 1>>>();

    const int threads = 256;
    const int blocks  = 148 * 8;
    topo_loss_reduce_kernel<<<blocks, threads>>>(inp, w, ref, mask, n4);

    finalize_kernel<<<1, 1>>>(out, n);
}

// round 3
// speedup vs baseline: 1.0017x; 1.0017x over previous
#include <cuda_runtime.h>
#include <cuda_bf16.h>

#define NBLOCKS (148 * 8)
#define NTHREADS 256

// Per-block partials + completion counter (reset to 0 by last block each launch)
__device__ float        g_psm[NBLOCKS];   // masked sum of sq_err
__device__ float        g_psf[NBLOCKS];   // full sum of sq_err
__device__ int          g_pcnt[NBLOCKS];  // mask count
__device__ unsigned int g_count = 0;

// Single fused kernel: grid-stride vectorized reduce + last-block finalize.
// inputs is (N, 2) float32 -> lik[i] = inputs[2*i + 1].
// mask is int32 per element.
__global__ __launch_bounds__(NTHREADS) void topo_loss_kernel(
    const float4* __restrict__ inp,   // N/2 float4s
    const float4* __restrict__ w,     // N/4 float4s
    const float4* __restrict__ ref,   // N/4 float4s
    const int4*   __restrict__ mask,  // N/4 int4s
    int n4,                           // N / 4
    int n_total,
    float* __restrict__ out)
{
    float sm = 0.0f;
    float sf = 0.0f;
    int   cnt = 0;

    const int stride = gridDim.x * blockDim.x;
    for (int i = blockIdx.x * blockDim.x + threadIdx.x; i < n4; i += stride) {
        float4 a = inp[2 * i];       // elems 4i, 4i+1 : (c0, c1, c0, c1)
        float4 b = inp[2 * i + 1];   // elems 4i+2, 4i+3
        float4 wv = w[i];
        float4 rv = ref[i];
        int4   mv = mask[i];

        float e0 = a.y * wv.x - rv.x;
        float e1 = a.w * wv.y - rv.y;
        float e2 = b.y * wv.z - rv.z;
        float e3 = b.w * wv.w - rv.w;

        float s0 = e0 * e0;
        float s1 = e1 * e1;
        float s2 = e2 * e2;
        float s3 = e3 * e3;

        sf += s0 + s1 + s2 + s3;

        sm += (mv.x ? s0 : 0.0f) + (mv.y ? s1 : 0.0f)
            + (mv.z ? s2 : 0.0f) + (mv.w ? s3 : 0.0f);
        cnt += (mv.x ? 1 : 0) + (mv.y ? 1 : 0) + (mv.z ? 1 : 0) + (mv.w ? 1 : 0);
    }

    // Warp reduction
    #pragma unroll
    for (int off = 16; off > 0; off >>= 1) {
        sm  += __shfl_down_sync(0xFFFFFFFFu, sm, off);
        sf  += __shfl_down_sync(0xFFFFFFFFu, sf, off);
        cnt += __shfl_down_sync(0xFFFFFFFFu, cnt, off);
    }

    __shared__ float s_sm[8];
    __shared__ float s_sf[8];
    __shared__ int   s_cnt[8];
    __shared__ int   s_is_last;

    const int lane = threadIdx.x & 31;
    const int wid  = threadIdx.x >> 5;
    if (lane == 0) {
        s_sm[wid]  = sm;
        s_sf[wid]  = sf;
        s_cnt[wid] = cnt;
    }
    __syncthreads();

    if (threadIdx.x == 0) {
        float bsm = 0.0f, bsf = 0.0f;
        int bcnt = 0;
        #pragma unroll
        for (int k = 0; k < NTHREADS / 32; k++) {
            bsm += s_sm[k];
            bsf += s_sf[k];
            bcnt += s_cnt[k];
        }
        g_psm[blockIdx.x]  = bsm;
        g_psf[blockIdx.x]  = bsf;
        g_pcnt[blockIdx.x] = bcnt;
        __threadfence();
        unsigned int prev = atomicAdd(&g_count, 1u);
        s_is_last = (prev == gridDim.x - 1);
    }
    __syncthreads();

    if (s_is_last) {
        // Final reduction of NBLOCKS partials (double precision)
        double dsm = 0.0, dsf = 0.0, dcnt = 0.0;
        for (int k = threadIdx.x; k < NBLOCKS; k += NTHREADS) {
            dsm  += (double)g_psm[k];
            dsf  += (double)g_psf[k];
            dcnt += (double)g_pcnt[k];
        }
        #pragma unroll
        for (int off = 16; off > 0; off >>= 1) {
            dsm  += __shfl_down_sync(0xFFFFFFFFu, dsm, off);
            dsf  += __shfl_down_sync(0xFFFFFFFFu, dsf, off);
            dcnt += __shfl_down_sync(0xFFFFFFFFu, dcnt, off);
        }

        __shared__ double f_sm[8];
        __shared__ double f_sf[8];
        __shared__ double f_cnt[8];
        if (lane == 0) {
            f_sm[wid]  = dsm;
            f_sf[wid]  = dsf;
            f_cnt[wid] = dcnt;
        }
        __syncthreads();

        if (threadIdx.x == 0) {
            double tsm = 0.0, tsf = 0.0, tcnt = 0.0;
            #pragma unroll
            for (int k = 0; k < NTHREADS / 32; k++) {
                tsm += f_sm[k];
                tsf += f_sf[k];
                tcnt += f_cnt[k];
            }
            double masked_mean = tsm / (tcnt > 1.0 ? tcnt : 1.0);
            double full_mean   = tsf / (double)n_total;
            out[0] = (float)((tcnt > 0.0) ? masked_mean : full_mean);
            g_count = 0;  // reset for next graph replay
        }
    }
}

extern "C" void kernel_launch(void* const* d_in, const int* in_sizes, int n_in,
                              void* d_out, int out_size) {
    // 0: inputs (N*2 f32), 1: weight (N f32), 2: ref (N f32), 3: mask (N int32)
    const float4* inp  = (const float4*)d_in[0];
    const float4* w    = (const float4*)d_in[1];
    const float4* ref  = (const float4*)d_in[2];
    const int4*   mask = (const int4*)d_in[3];
    float* out = (float*)d_out;

    const int n  = in_sizes[1];   // total elements (B*H*W)
    const int n4 = n / 4;

    topo_loss_kernel<<<NBLOCKS, NTHREADS>>>(inp, w, ref, mask, n4, n, out);
}